// round 9
// baseline (speedup 1.0000x reference)
#include <cuda_runtime.h>
#include <cuda_fp16.h>
#include <cstdint>

#define NN      50000
#define EE      1600000
#define KP      25
#define KALL    26
#define FOUT    64
#define PADR    72                    // W-buffer row pad (halves)
#define SLICE_W 328                   // stage row: 5*64 + 8 pad (halves)
#define NBLK    ((NN + 1023) / 1024)

// ---------------- device scratch ----------------
__device__ __half g_xh[(size_t)NN * 64];
__device__ __half g_wt[KALL * 64 * 64];          // W^T [k][o][i]; k=25 is root
__device__ __half g_xwroot[(size_t)NN * 64];     // x @ root (fp16)
__device__ float  g_deg[NN];
__device__ int    g_cnt[NN];
__device__ int    g_off[NN];                     // post-prep: exclusive END per col
__device__ int    g_bsum[NBLK];
__device__ uint4  g_erec[EE];                    // col-sorted edge records

// ---------------- helpers ----------------
__device__ __forceinline__ uint32_t smem_u32(const void* p) {
    uint32_t a;
    asm("{ .reg .u64 t; cvta.to.shared.u64 t, %1; cvt.u32.u64 %0, t; }"
        : "=r"(a) : "l"(p));
    return a;
}
__device__ __forceinline__ void ldsm_x4(uint32_t addr, uint32_t* r) {
    asm volatile("ldmatrix.sync.aligned.m8n8.x4.shared.b16 {%0,%1,%2,%3}, [%4];"
                 : "=r"(r[0]), "=r"(r[1]), "=r"(r[2]), "=r"(r[3]) : "r"(addr));
}
__device__ __forceinline__ void mma_f16(float* c, const uint32_t* a, const uint32_t* b) {
    asm volatile(
        "mma.sync.aligned.m16n8k16.row.col.f32.f16.f16.f32 "
        "{%0,%1,%2,%3}, {%4,%5,%6,%7}, {%8,%9}, {%0,%1,%2,%3};"
        : "+f"(c[0]), "+f"(c[1]), "+f"(c[2]), "+f"(c[3])
        : "r"(a[0]), "r"(a[1]), "r"(a[2]), "r"(a[3]), "r"(b[0]), "r"(b[1]));
}

// ---------------- prep ----------------
__global__ void prep_x(const float* __restrict__ x, float* __restrict__ out) {
    int i = blockIdx.x * blockDim.x + threadIdx.x;
    if (i >= NN * 64) return;
    g_xh[i] = __float2half(x[i]);
    out[i] = 0.0f;
    if (i < NN) { g_deg[i] = 0.0f; g_cnt[i] = 0; }
}
__global__ void prep_w(const float* __restrict__ w, const float* __restrict__ root) {
    int i = blockIdx.x * blockDim.x + threadIdx.x;
    if (i >= KALL * 64 * 64) return;
    int k = i >> 12, rem = i & 4095;
    int ii = rem >> 6, o = rem & 63;
    float v = (k < KP) ? w[i] : root[rem];
    g_wt[(k << 12) + (o << 6) + ii] = __float2half(v);
}
__global__ __launch_bounds__(256) void hist_kernel(const int* __restrict__ ei) {
    int e = blockIdx.x * blockDim.x + threadIdx.x;
    if (e < EE) atomicAdd(&g_cnt[ei[EE + e]], 1);
}
__global__ __launch_bounds__(1024) void scan_local() {
    __shared__ int wsum[32];
    int idx  = blockIdx.x * 1024 + threadIdx.x;
    int lane = threadIdx.x & 31;
    int wid  = threadIdx.x >> 5;
    int v = (idx < NN) ? g_cnt[idx] : 0;
    int s = v;
    #pragma unroll
    for (int o = 1; o < 32; o <<= 1) {
        int t = __shfl_up_sync(0xFFFFFFFFu, s, o);
        if (lane >= o) s += t;
    }
    if (lane == 31) wsum[wid] = s;
    __syncthreads();
    if (wid == 0) {
        int ws = wsum[lane];
        #pragma unroll
        for (int o = 1; o < 32; o <<= 1) {
            int t = __shfl_up_sync(0xFFFFFFFFu, ws, o);
            if (lane >= o) ws += t;
        }
        wsum[lane] = ws;
    }
    __syncthreads();
    int excl = s - v + (wid > 0 ? wsum[wid - 1] : 0);
    if (idx < NN) g_off[idx] = excl;
    if (threadIdx.x == 1023) g_bsum[blockIdx.x] = excl + v;
}
__global__ __launch_bounds__(64) void scan_tops() {
    __shared__ int s[64];
    int tid = threadIdx.x;
    s[tid] = (tid < NBLK) ? g_bsum[tid] : 0;
    __syncthreads();
    if (tid == 0) {
        int acc = 0;
        #pragma unroll 1
        for (int i = 0; i < NBLK; i++) { int t = s[i]; s[i] = acc; acc += t; }
    }
    __syncthreads();
    if (tid < NBLK) g_bsum[tid] = s[tid];
}
__global__ __launch_bounds__(1024) void scan_add() {
    int idx = blockIdx.x * 1024 + threadIdx.x;
    if (idx < NN) g_off[idx] += g_bsum[blockIdx.x];
}
// record: {row*64, col, i0|i1<<8, frac half2}; scattered to col-sorted slots
__global__ __launch_bounds__(256) void prep_edges(const int* __restrict__ ei,
                                                  const float* __restrict__ ps) {
    int e = blockIdx.x * blockDim.x + threadIdx.x;
    if (e >= EE) return;
    int row = ei[e];
    int col = ei[EE + e];
    float2 p = *(const float2*)(ps + 2 * e);
    float v0 = p.x * 4.0f, v1 = p.y * 4.0f;
    float fl0 = floorf(v0), fl1 = floorf(v1);
    float f0 = v0 - fl0, f1 = v1 - fl1;
    int i0 = (int)fl0, i1 = (int)fl1;            // 0..3
    __half2 fh = __floats2half2_rn(f0, f1);
    uint4 rec;
    rec.x = (unsigned)(row * FOUT);
    rec.y = (unsigned)col;
    rec.z = (unsigned)(i0 | (i1 << 8));
    rec.w = *(unsigned*)&fh;
    int slot = atomicAdd(&g_off[col], 1);        // g_off becomes exclusive END
    g_erec[slot] = rec;
    atomicAdd(&g_deg[row], 1.0f);
}

// ---------------------------------------------------------------------------
// FUSED: per 128-col block, for each k-slice (grid row j: k=5j..5j+4):
//   MMA xw slice into smem stage, then blend+scatter this block's edges whose
//   spline rows i0/i0+1 == j (2 cells each) straight from smem.
//   Slice 5 = root (k=25) -> written to g_xwroot.
// ---------------------------------------------------------------------------
__global__ __launch_bounds__(256) void fused_kernel(float* __restrict__ out) {
    extern __shared__ __half sm[];
    __half* xs = sm;                     // [128][SLICE_W]: x tile, then stage
    __half* ws = sm + 128 * SLICE_W;     // [64][PADR]

    const int tid  = threadIdx.x;
    const int wid  = tid >> 5;
    const int lane = tid & 31;
    const int n0   = blockIdx.x * 128;

    // ---- x tile ----
    #pragma unroll
    for (int it = 0; it < 4; it++) {
        int flat = tid + 256 * it;
        int r = flat >> 3, j = flat & 7;
        int gn = n0 + r;
        uint4 v = make_uint4(0, 0, 0, 0);
        if (gn < NN) v = *(const uint4*)(g_xh + (size_t)gn * 64 + j * 8);
        *(uint4*)(xs + r * SLICE_W + j * 8) = v;
    }
    __syncthreads();

    // ---- hoist A fragments ----
    const int m0    = wid * 16;
    const int a_row = m0 + (lane & 15);
    const int a_c8  = (lane >> 4) * 8;
    uint32_t ah[4][4];
    #pragma unroll
    for (int ks = 0; ks < 4; ks++)
        ldsm_x4(smem_u32(xs + a_row * SLICE_W + ks * 16 + a_c8), ah[ks]);
    __syncthreads();   // all A reads done; xs is now the stage buffer

    const int bw_r = lane & 7;
    const int bw_g = lane >> 3;
    const int g  = lane >> 2;
    const int t2 = (lane & 3) * 2;

    // ---- edge range for this col block (CSR via g_off ends) ----
    const int cl = (n0 + 127 < NN) ? n0 + 127 : NN - 1;
    const int es = (blockIdx.x == 0) ? 0 : g_off[n0 - 1];
    const int ee = g_off[cl];
    const int halfid = lane >> 4;
    const int sub4   = (lane & 15) * 4;

    for (int j = 0; j < 6; j++) {
        const int nk = (j < 5) ? 5 : 1;
        for (int kk = 0; kk < nk; kk++) {
            const int k = (j < 5) ? j * 5 + kk : 25;
            __syncthreads();                       // prior ws readers / xs readers done
            #pragma unroll
            for (int it = 0; it < 2; it++) {
                int flat = tid + 256 * it;
                int r = flat >> 3, jc = flat & 7;
                *(uint4*)(ws + r * PADR + jc * 8) =
                    *(const uint4*)(g_wt + (k << 12) + r * 64 + jc * 8);
            }
            __syncthreads();
            #pragma unroll
            for (int nt = 0; nt < 8; nt++) {
                float acc[4] = {0.f, 0.f, 0.f, 0.f};
                uint32_t bh[8];
                uint32_t row_off = (nt * 8 + bw_r) * PADR + bw_g * 8;
                ldsm_x4(smem_u32(ws + row_off), bh);
                ldsm_x4(smem_u32(ws + row_off + 32), bh + 4);
                #pragma unroll
                for (int ks = 0; ks < 4; ks++)
                    mma_f16(acc, ah[ks], bh + ks * 2);
                __half2 h01 = __floats2half2_rn(acc[0], acc[1]);
                __half2 h23 = __floats2half2_rn(acc[2], acc[3]);
                *(__half2*)(xs + (m0 + g) * SLICE_W + kk * 64 + nt * 8 + t2)     = h01;
                *(__half2*)(xs + (m0 + g + 8) * SLICE_W + kk * 64 + nt * 8 + t2) = h23;
            }
        }
        __syncthreads();   // stage complete

        if (j < 5) {
            // ---- edge pass: half-warp per edge ----
            for (int e = es + wid * 2 + halfid; e < ee; e += 16) {
                uint4 rec = g_erec[e];
                int i0 = rec.z & 255;
                int d  = j - i0;
                if ((unsigned)d <= 1u) {
                    int i1 = (rec.z >> 8) & 255;
                    __half2 fh = *(const __half2*)&rec.w;
                    float f0 = __low2float(fh), f1 = __high2float(fh);
                    float w0 = d ? f0 : (1.0f - f0);
                    __half2 wA = __float2half2_rn(w0 * (1.0f - f1));
                    __half2 wB = __float2half2_rn(w0 * f1);
                    int local = (int)rec.y - n0;
                    const __half* p = xs + local * SLICE_W + i1 * 64 + sub4;
                    uint2 ua = *(const uint2*)p;
                    uint2 ub = *(const uint2*)(p + 64);
                    __half2 r0 = __hmul2(wA, *(__half2*)&ua.x);
                    r0 = __hfma2(wB, *(__half2*)&ub.x, r0);
                    __half2 r1 = __hmul2(wA, *(__half2*)&ua.y);
                    r1 = __hfma2(wB, *(__half2*)&ub.y, r1);
                    float2 lo = __half22float2(r0);
                    float2 hi = __half22float2(r1);
                    float* op = out + rec.x + sub4;
                    asm volatile("red.global.add.v4.f32 [%0], {%1, %2, %3, %4};"
                                 :: "l"(op), "f"(lo.x), "f"(lo.y), "f"(hi.x), "f"(hi.y)
                                 : "memory");
                }
            }
        } else {
            // ---- root slice: stage cols 0..63 -> g_xwroot ----
            #pragma unroll
            for (int it = 0; it < 4; it++) {
                int flat = tid + 256 * it;
                int r = flat >> 3, jc = flat & 7;
                int gn = n0 + r;
                if (gn < NN)
                    *(uint4*)(g_xwroot + (size_t)gn * 64 + jc * 8) =
                        *(const uint4*)(xs + r * SLICE_W + jc * 8);
            }
        }
    }
}

// ---------------------------------------------------------------------------
// final: out = out/max(deg,1) + xwroot + bias
// ---------------------------------------------------------------------------
__global__ __launch_bounds__(256) void final_kernel(const float* __restrict__ bias,
                                                    float* __restrict__ out) {
    int i = blockIdx.x * 256 + threadIdx.x;
    if (i >= NN * 16) return;
    int n  = i >> 4;
    int c4 = (i & 15) * 4;
    float scale = 1.0f / fmaxf(g_deg[n], 1.0f);
    float4 o = *(float4*)(out + n * FOUT + c4);
    uint2 hu = *(const uint2*)(g_xwroot + (size_t)n * 64 + c4);
    float2 rl = __half22float2(*(__half2*)&hu.x);
    float2 rh = __half22float2(*(__half2*)&hu.y);
    float4 b = *(const float4*)(bias + c4);
    o.x = o.x * scale + rl.x + b.x;
    o.y = o.y * scale + rl.y + b.y;
    o.z = o.z * scale + rh.x + b.z;
    o.w = o.w * scale + rh.y + b.w;
    *(float4*)(out + n * FOUT + c4) = o;
}

// ---------------------------------------------------------------------------
extern "C" void kernel_launch(void* const* d_in, const int* in_sizes, int n_in,
                              void* d_out, int out_size) {
    const float* x      = (const float*)d_in[0];
    const int*   ei     = (const int*)  d_in[1];
    const float* pseudo = (const float*)d_in[2];
    const float* weight = (const float*)d_in[3];
    const float* root   = (const float*)d_in[4];
    const float* bias   = (const float*)d_in[5];
    float* out = (float*)d_out;

    const int smem_bytes = (128 * SLICE_W + 64 * PADR) * (int)sizeof(__half);
    cudaFuncSetAttribute(fused_kernel, cudaFuncAttributeMaxDynamicSharedMemorySize,
                         smem_bytes);

    prep_x<<<(NN * 64 + 255) / 256, 256>>>(x, out);
    prep_w<<<(KALL * 64 * 64 + 255) / 256, 256>>>(weight, root);
    hist_kernel<<<(EE + 255) / 256, 256>>>(ei);
    scan_local<<<NBLK, 1024>>>();
    scan_tops<<<1, 64>>>();
    scan_add<<<NBLK, 1024>>>();
    prep_edges<<<(EE + 255) / 256, 256>>>(ei, pseudo);

    fused_kernel<<<(NN + 127) / 128, 256, smem_bytes>>>(out);

    final_kernel<<<(NN * 16 + 255) / 256, 256>>>(bias, out);
}

// round 10
// speedup vs baseline: 3.1478x; 3.1478x over previous
#include <cuda_runtime.h>
#include <cuda_fp16.h>
#include <cstdint>

#define NN    50000
#define EE    1600000
#define KP    25
#define KALL  26                    // 25 spline mats + root
#define FOUT  64
#define KROW  (KALL * FOUT)         // 1664 halves per node row
#define PADR  72                    // row pad (half): 144B rows, LDSM conflict-free
#define NBLK  ((NN + 1023) / 1024)  // scan blocks

// ---------------- device scratch (no runtime allocation allowed) -----------
__device__ __half g_xh[(size_t)NN * 64];
__device__ __half g_wt[KALL * 64 * 64];          // fp16 W^T: [k][o][i], k=25 is root
__device__ __half g_xw[(size_t)NN * KROW];       // 166 MB fp16 table
__device__ float  g_deg[NN];
__device__ int    g_cnt[NN];
__device__ int    g_off[NN];
__device__ int    g_bsum[NBLK];
__device__ uint4  g_erec[EE];                    // edge records (col-sorted)

// ---------------- helpers ---------------------------------------------------
__device__ __forceinline__ uint32_t smem_u32(const void* p) {
    uint32_t a;
    asm("{ .reg .u64 t; cvta.to.shared.u64 t, %1; cvt.u32.u64 %0, t; }"
        : "=r"(a) : "l"(p));
    return a;
}
__device__ __forceinline__ void ldsm_x4(uint32_t addr, uint32_t* r) {
    asm volatile("ldmatrix.sync.aligned.m8n8.x4.shared.b16 {%0,%1,%2,%3}, [%4];"
                 : "=r"(r[0]), "=r"(r[1]), "=r"(r[2]), "=r"(r[3]) : "r"(addr));
}
__device__ __forceinline__ void mma_f16(float* c, const uint32_t* a, const uint32_t* b) {
    asm volatile(
        "mma.sync.aligned.m16n8k16.row.col.f32.f16.f16.f32 "
        "{%0,%1,%2,%3}, {%4,%5,%6,%7}, {%8,%9}, {%0,%1,%2,%3};"
        : "+f"(c[0]), "+f"(c[1]), "+f"(c[2]), "+f"(c[3])
        : "r"(a[0]), "r"(a[1]), "r"(a[2]), "r"(a[3]), "r"(b[0]), "r"(b[1]));
}

// ---------------------------------------------------------------------------
// prep kernels
// ---------------------------------------------------------------------------
__global__ void prep_x(const float* __restrict__ x, float* __restrict__ out) {
    int i = blockIdx.x * blockDim.x + threadIdx.x;
    if (i >= NN * 64) return;
    g_xh[i] = __float2half(x[i]);
    out[i] = 0.0f;
    if (i < NN) { g_deg[i] = 0.0f; g_cnt[i] = 0; }
}
__global__ void prep_w(const float* __restrict__ w, const float* __restrict__ root) {
    int i = blockIdx.x * blockDim.x + threadIdx.x;
    if (i >= KALL * 64 * 64) return;
    int k = i >> 12, rem = i & 4095;
    int ii = rem >> 6, o = rem & 63;
    float v = (k < KP) ? w[i] : root[rem];
    g_wt[(k << 12) + (o << 6) + ii] = __float2half(v);    // [k][o][i]
}
__global__ __launch_bounds__(256) void hist_kernel(const int* __restrict__ ei) {
    int e = blockIdx.x * blockDim.x + threadIdx.x;
    if (e < EE) atomicAdd(&g_cnt[ei[EE + e]], 1);
}
// ---- 3-pass device scan ----
__global__ __launch_bounds__(1024) void scan_local() {
    __shared__ int wsum[32];
    int idx  = blockIdx.x * 1024 + threadIdx.x;
    int lane = threadIdx.x & 31;
    int wid  = threadIdx.x >> 5;
    int v = (idx < NN) ? g_cnt[idx] : 0;
    int s = v;
    #pragma unroll
    for (int o = 1; o < 32; o <<= 1) {
        int t = __shfl_up_sync(0xFFFFFFFFu, s, o);
        if (lane >= o) s += t;
    }
    if (lane == 31) wsum[wid] = s;
    __syncthreads();
    if (wid == 0) {
        int ws = wsum[lane];
        #pragma unroll
        for (int o = 1; o < 32; o <<= 1) {
            int t = __shfl_up_sync(0xFFFFFFFFu, ws, o);
            if (lane >= o) ws += t;
        }
        wsum[lane] = ws;
    }
    __syncthreads();
    int excl = s - v + (wid > 0 ? wsum[wid - 1] : 0);
    if (idx < NN) g_off[idx] = excl;
    if (threadIdx.x == 1023) g_bsum[blockIdx.x] = excl + v;
}
__global__ __launch_bounds__(64) void scan_tops() {
    __shared__ int s[64];
    int tid = threadIdx.x;
    s[tid] = (tid < NBLK) ? g_bsum[tid] : 0;
    __syncthreads();
    if (tid == 0) {
        int acc = 0;
        #pragma unroll 1
        for (int i = 0; i < NBLK; i++) { int t = s[i]; s[i] = acc; acc += t; }
    }
    __syncthreads();
    if (tid < NBLK) g_bsum[tid] = s[tid];
}
__global__ __launch_bounds__(1024) void scan_add() {
    int idx = blockIdx.x * 1024 + threadIdx.x;
    if (idx < NN) g_off[idx] += g_bsum[blockIdx.x];
}
// per-edge scalar math + col-sorted record scatter + degree atomic
__global__ __launch_bounds__(256) void prep_edges(const int* __restrict__ ei,
                                                  const float* __restrict__ ps) {
    int e = blockIdx.x * blockDim.x + threadIdx.x;
    if (e >= EE) return;
    int row = ei[e];
    int col = ei[EE + e];
    float2 p = *(const float2*)(ps + 2 * e);
    float v0 = p.x * 4.0f, v1 = p.y * 4.0f;
    float fl0 = floorf(v0), fl1 = floorf(v1);
    float f0 = v0 - fl0, f1 = v1 - fl1;
    int i0 = (int)fl0, i1 = (int)fl1;            // 0..3, +1 in range
    unsigned c00 = (unsigned)(i0 * 5 + i1);
    unsigned cells = c00 | ((c00 + 5u) << 8) | ((c00 + 1u) << 16) | ((c00 + 6u) << 24);
    __half2 fh = __floats2half2_rn(f0, f1);
    uint4 rec;
    rec.x = (unsigned)(row * FOUT);
    rec.y = (unsigned)(col * KROW);
    rec.z = cells;
    rec.w = *(unsigned*)&fh;
    int slot = atomicAdd(&g_off[col], 1);
    g_erec[slot] = rec;
    atomicAdd(&g_deg[row], 1.0f);
}

// ---------------------------------------------------------------------------
// xw[n,k,:] = x[n,:] @ W[k], k=0..25 (25=root). Single-pass fp16 mma.
// 512 threads, 256-node tiles (halves W traffic vs 128-node tiles).
// grid.y: 0..4 -> 5 slices each; 5 -> 1 slice (k=25).
// ---------------------------------------------------------------------------
__global__ __launch_bounds__(512) void xw_mma() {
    extern __shared__ __half sm[];
    __half* xs = sm;                   // [256][PADR]; reused as epilogue stage
    __half* ws = sm + 256 * PADR;      // [64][PADR]

    const int tid  = threadIdx.x;
    const int wid  = tid >> 5;
    const int lane = tid & 31;
    const int n0   = blockIdx.x * 256;
    const int kbeg = blockIdx.y * 5;
    const int kcnt = (blockIdx.y == 5) ? 1 : 5;

    // load x tile (256 rows x 8 uint4)
    #pragma unroll
    for (int it = 0; it < 4; it++) {
        int flat = tid + 512 * it;
        int r = flat >> 3, j = flat & 7;
        int gn = n0 + r;
        uint4 v = make_uint4(0, 0, 0, 0);
        if (gn < NN) v = *(const uint4*)(g_xh + (size_t)gn * 64 + j * 8);
        *(uint4*)(xs + r * PADR + j * 8) = v;
    }
    __syncthreads();

    const int m0    = wid * 16;
    const int a_row = m0 + (lane & 15);
    const int a_c8  = (lane >> 4) * 8;
    uint32_t ah[4][4];
    #pragma unroll
    for (int ks = 0; ks < 4; ks++)
        ldsm_x4(smem_u32(xs + a_row * PADR + ks * 16 + a_c8), ah[ks]);

    const int bw_r = lane & 7;
    const int bw_g = lane >> 3;
    const int g  = lane >> 2;
    const int t2 = (lane & 3) * 2;

    for (int j = 0; j < kcnt; j++) {
        const int k = kbeg + j;
        __syncthreads();
        // load W^T[k] (64 rows x 8 uint4 = 512 loads, one per thread)
        {
            int r = tid >> 3, jc = tid & 7;
            *(uint4*)(ws + r * PADR + jc * 8) =
                *(const uint4*)(g_wt + (k << 12) + r * 64 + jc * 8);
        }
        __syncthreads();

        #pragma unroll
        for (int nt = 0; nt < 8; nt++) {
            float acc[4] = {0.f, 0.f, 0.f, 0.f};
            uint32_t bh[8];
            uint32_t row_off = (nt * 8 + bw_r) * PADR + bw_g * 8;
            ldsm_x4(smem_u32(ws + row_off), bh);
            ldsm_x4(smem_u32(ws + row_off + 32), bh + 4);
            #pragma unroll
            for (int ks = 0; ks < 4; ks++)
                mma_f16(acc, ah[ks], bh + ks * 2);
            __half2 h01 = __floats2half2_rn(acc[0], acc[1]);
            __half2 h23 = __floats2half2_rn(acc[2], acc[3]);
            *(__half2*)(xs + (m0 + g) * PADR + nt * 8 + t2)     = h01;
            *(__half2*)(xs + (m0 + g + 8) * PADR + nt * 8 + t2) = h23;
        }
        __syncthreads();
        // coalesced copy-out: 256 rows x 128B
        #pragma unroll
        for (int it = 0; it < 4; it++) {
            int flat = tid + 512 * it;
            int r = flat >> 3, jc = flat & 7;
            int gn = n0 + r;
            if (gn < NN)
                *(uint4*)(g_xw + (size_t)gn * KROW + k * 64 + jc * 8) =
                    *(const uint4*)(xs + r * PADR + jc * 8);
        }
    }
}

// ---------------------------------------------------------------------------
// edge pass: half-warp per edge; 16 lanes x 4 halves; fp16 blend; red.v4.f32
// ---------------------------------------------------------------------------
__global__ __launch_bounds__(256) void edge_kernel(float* __restrict__ out) {
    const int warp   = (blockIdx.x * blockDim.x + threadIdx.x) >> 5;
    const int lane   = threadIdx.x & 31;
    const int half   = lane >> 4;
    const int sub4   = (lane & 15) * 4;
    const int nwarps = (gridDim.x * blockDim.x) >> 5;

    for (int e = warp * 2 + half; e < EE; e += nwarps * 2) {
        uint4 rec = g_erec[e];
        const __half* p = g_xw + rec.y + sub4;
        unsigned c = rec.z;

        uint2 Au = *(const uint2*)(p + ((c & 255u) << 6));
        uint2 Bu = *(const uint2*)(p + (((c >> 8) & 255u) << 6));
        uint2 Cu = *(const uint2*)(p + (((c >> 16) & 255u) << 6));
        uint2 Du = *(const uint2*)(p + ((c >> 24) << 6));

        __half2 fh = *(const __half2*)&rec.w;
        float f0 = __low2float(fh), f1 = __high2float(fh);
        float g0 = 1.0f - f0, g1 = 1.0f - f1;
        __half2 w00 = __float2half2_rn(g0 * g1);
        __half2 w10 = __float2half2_rn(f0 * g1);
        __half2 w01 = __float2half2_rn(g0 * f1);
        __half2 w11 = __float2half2_rn(f0 * f1);

        __half2 A0 = *(__half2*)&Au.x, A1 = *(__half2*)&Au.y;
        __half2 B0 = *(__half2*)&Bu.x, B1 = *(__half2*)&Bu.y;
        __half2 C0 = *(__half2*)&Cu.x, C1 = *(__half2*)&Cu.y;
        __half2 D0 = *(__half2*)&Du.x, D1 = *(__half2*)&Du.y;

        __half2 r0 = __hmul2(w00, A0);
        r0 = __hfma2(w10, B0, r0);
        r0 = __hfma2(w01, C0, r0);
        r0 = __hfma2(w11, D0, r0);
        __half2 r1 = __hmul2(w00, A1);
        r1 = __hfma2(w10, B1, r1);
        r1 = __hfma2(w01, C1, r1);
        r1 = __hfma2(w11, D1, r1);

        float2 lo = __half22float2(r0);
        float2 hi = __half22float2(r1);
        float* op = out + rec.x + sub4;
        asm volatile("red.global.add.v4.f32 [%0], {%1, %2, %3, %4};"
                     :: "l"(op), "f"(lo.x), "f"(lo.y), "f"(hi.x), "f"(hi.y)
                     : "memory");
    }
}

// ---------------------------------------------------------------------------
// final (elementwise): out = out/max(deg,1) + xw[n,25,:] + bias
// ---------------------------------------------------------------------------
__global__ __launch_bounds__(256) void final_kernel(const float* __restrict__ bias,
                                                    float* __restrict__ out) {
    int i = blockIdx.x * 256 + threadIdx.x;
    if (i >= NN * 16) return;
    int n  = i >> 4;
    int c4 = (i & 15) * 4;
    float scale = 1.0f / fmaxf(g_deg[n], 1.0f);
    float4 o = *(float4*)(out + n * FOUT + c4);
    uint2 hu = *(const uint2*)(g_xw + (size_t)n * KROW + KP * 64 + c4);
    float2 rl = __half22float2(*(__half2*)&hu.x);
    float2 rh = __half22float2(*(__half2*)&hu.y);
    float4 b = *(const float4*)(bias + c4);
    o.x = o.x * scale + rl.x + b.x;
    o.y = o.y * scale + rl.y + b.y;
    o.z = o.z * scale + rh.x + b.z;
    o.w = o.w * scale + rh.y + b.w;
    *(float4*)(out + n * FOUT + c4) = o;
}

// ---------------------------------------------------------------------------
extern "C" void kernel_launch(void* const* d_in, const int* in_sizes, int n_in,
                              void* d_out, int out_size) {
    const float* x      = (const float*)d_in[0];
    const int*   ei     = (const int*)  d_in[1];
    const float* pseudo = (const float*)d_in[2];
    const float* weight = (const float*)d_in[3];
    const float* root   = (const float*)d_in[4];
    const float* bias   = (const float*)d_in[5];
    float* out = (float*)d_out;

    const int smem_bytes = (256 * PADR + 64 * PADR) * (int)sizeof(__half);
    cudaFuncSetAttribute(xw_mma, cudaFuncAttributeMaxDynamicSharedMemorySize, smem_bytes);

    prep_x<<<(NN * 64 + 255) / 256, 256>>>(x, out);
    prep_w<<<(KALL * 64 * 64 + 255) / 256, 256>>>(weight, root);
    hist_kernel<<<(EE + 255) / 256, 256>>>(ei);
    scan_local<<<NBLK, 1024>>>();
    scan_tops<<<1, 64>>>();
    scan_add<<<NBLK, 1024>>>();
    prep_edges<<<(EE + 255) / 256, 256>>>(ei, pseudo);

    dim3 g2((NN + 255) / 256, 6);
    xw_mma<<<g2, 512, smem_bytes>>>();

    edge_kernel<<<6144, 256>>>(out);

    final_kernel<<<(NN * 16 + 255) / 256, 256>>>(bias, out);
}

// round 11
// speedup vs baseline: 3.5382x; 1.1240x over previous
#include <cuda_runtime.h>
#include <cuda_fp16.h>
#include <cstdint>

#define NN    50000
#define EE    1600000
#define KP    25
#define KALL  26                    // 25 spline mats + root
#define FOUT  64
#define KROW  (KALL * FOUT)         // 1664 halves per node row
#define PADR  72                    // row pad (half): 144B rows, LDSM conflict-free
#define NBLK  ((NN + 1023) / 1024)  // scan blocks

// ---------------- device scratch (no runtime allocation allowed) -----------
__device__ __half g_xh[(size_t)NN * 64];
__device__ __half g_wt[KALL * 64 * 64];          // fp16 W^T: [k][o][i], k=25 is root
__device__ __half g_xw[(size_t)NN * KROW];       // 166 MB fp16 table
__device__ float  g_deg[NN];
__device__ int    g_cnt[NN];                     // zero-init; re-zeroed by scan_local
__device__ int    g_off[NN];
__device__ int    g_bsum[NBLK];
__device__ uint4  g_erec[EE];                    // edge records (col-sorted)

// ---------------- helpers ---------------------------------------------------
__device__ __forceinline__ uint32_t smem_u32(const void* p) {
    uint32_t a;
    asm("{ .reg .u64 t; cvta.to.shared.u64 t, %1; cvt.u32.u64 %0, t; }"
        : "=r"(a) : "l"(p));
    return a;
}
__device__ __forceinline__ void ldsm_x4(uint32_t addr, uint32_t* r) {
    asm volatile("ldmatrix.sync.aligned.m8n8.x4.shared.b16 {%0,%1,%2,%3}, [%4];"
                 : "=r"(r[0]), "=r"(r[1]), "=r"(r[2]), "=r"(r[3]) : "r"(addr));
}
__device__ __forceinline__ void mma_f16(float* c, const uint32_t* a, const uint32_t* b) {
    asm volatile(
        "mma.sync.aligned.m16n8k16.row.col.f32.f16.f16.f32 "
        "{%0,%1,%2,%3}, {%4,%5,%6,%7}, {%8,%9}, {%0,%1,%2,%3};"
        : "+f"(c[0]), "+f"(c[1]), "+f"(c[2]), "+f"(c[3])
        : "r"(a[0]), "r"(a[1]), "r"(a[2]), "r"(a[3]), "r"(b[0]), "r"(b[1]));
}

// ---------------------------------------------------------------------------
// fused prep (launch 0): x->fp16, out zero, deg zero, W^T->fp16, col histogram
// g_cnt is guaranteed zero at entry (zero-init / reset by previous scan_local).
// ---------------------------------------------------------------------------
__global__ __launch_bounds__(256) void fused_prep(const float* __restrict__ x,
                                                  const float* __restrict__ w,
                                                  const float* __restrict__ root,
                                                  const int*   __restrict__ ei,
                                                  float* __restrict__ out) {
    int i = blockIdx.x * blockDim.x + threadIdx.x;
    if (i < NN * 64) {
        g_xh[i] = __float2half(x[i]);
        out[i] = 0.0f;
    }
    if (i < NN) g_deg[i] = 0.0f;
    if (i < KALL * 64 * 64) {
        int k = i >> 12, rem = i & 4095;
        int ii = rem >> 6, o = rem & 63;
        float v = (k < KP) ? w[i] : root[rem];
        g_wt[(k << 12) + (o << 6) + ii] = __float2half(v);   // [k][o][i]
    }
    if (i < EE) atomicAdd(&g_cnt[ei[EE + i]], 1);
}

// ---- scan (launches 1,2): local shuffle scan (+cnt reset) -> tops scan ----
__global__ __launch_bounds__(1024) void scan_local() {
    __shared__ int wsum[32];
    int idx  = blockIdx.x * 1024 + threadIdx.x;
    int lane = threadIdx.x & 31;
    int wid  = threadIdx.x >> 5;
    int v = (idx < NN) ? g_cnt[idx] : 0;
    if (idx < NN) g_cnt[idx] = 0;                // reset for next launch/replay
    int s = v;
    #pragma unroll
    for (int o = 1; o < 32; o <<= 1) {
        int t = __shfl_up_sync(0xFFFFFFFFu, s, o);
        if (lane >= o) s += t;
    }
    if (lane == 31) wsum[wid] = s;
    __syncthreads();
    if (wid == 0) {
        int ws = wsum[lane];
        #pragma unroll
        for (int o = 1; o < 32; o <<= 1) {
            int t = __shfl_up_sync(0xFFFFFFFFu, ws, o);
            if (lane >= o) ws += t;
        }
        wsum[lane] = ws;
    }
    __syncthreads();
    int excl = s - v + (wid > 0 ? wsum[wid - 1] : 0);
    if (idx < NN) g_off[idx] = excl;             // block-local exclusive prefix
    if (threadIdx.x == 1023) g_bsum[blockIdx.x] = excl + v;
}
__global__ __launch_bounds__(64) void scan_tops() {
    __shared__ int s[64];
    int tid = threadIdx.x;
    s[tid] = (tid < NBLK) ? g_bsum[tid] : 0;
    __syncthreads();
    if (tid == 0) {
        int acc = 0;
        #pragma unroll 1
        for (int i = 0; i < NBLK; i++) { int t = s[i]; s[i] = acc; acc += t; }
    }
    __syncthreads();
    if (tid < NBLK) g_bsum[tid] = s[tid];
}

// ---------------------------------------------------------------------------
// prep_edges (launch 3): scalar spline math + col-sorted scatter + degree.
// slot = local prefix (atomic) + block base from g_bsum.
// ---------------------------------------------------------------------------
__global__ __launch_bounds__(256) void prep_edges(const int* __restrict__ ei,
                                                  const float* __restrict__ ps) {
    int e = blockIdx.x * blockDim.x + threadIdx.x;
    if (e >= EE) return;
    int row = ei[e];
    int col = ei[EE + e];
    float2 p = *(const float2*)(ps + 2 * e);
    float v0 = p.x * 4.0f, v1 = p.y * 4.0f;
    float fl0 = floorf(v0), fl1 = floorf(v1);
    float f0 = v0 - fl0, f1 = v1 - fl1;
    int i0 = (int)fl0, i1 = (int)fl1;            // 0..3, +1 in range
    unsigned c00 = (unsigned)(i0 * 5 + i1);
    unsigned cells = c00 | ((c00 + 5u) << 8) | ((c00 + 1u) << 16) | ((c00 + 6u) << 24);
    __half2 fh = __floats2half2_rn(f0, f1);
    uint4 rec;
    rec.x = (unsigned)(row * FOUT);
    rec.y = (unsigned)(col * KROW);
    rec.z = cells;
    rec.w = *(unsigned*)&fh;
    int slot = atomicAdd(&g_off[col], 1) + g_bsum[col >> 10];
    g_erec[slot] = rec;
    atomicAdd(&g_deg[row], 1.0f);
}

// ---------------------------------------------------------------------------
// xw_mma (launch 4): xw[n,k,:] = x[n,:] @ W[k]; 512 thr, 256-node tiles.
// ---------------------------------------------------------------------------
__global__ __launch_bounds__(512) void xw_mma() {
    extern __shared__ __half sm[];
    __half* xs = sm;                   // [256][PADR]; reused as epilogue stage
    __half* ws = sm + 256 * PADR;      // [64][PADR]

    const int tid  = threadIdx.x;
    const int wid  = tid >> 5;
    const int lane = tid & 31;
    const int n0   = blockIdx.x * 256;
    const int kbeg = blockIdx.y * 5;
    const int kcnt = (blockIdx.y == 5) ? 1 : 5;

    #pragma unroll
    for (int it = 0; it < 4; it++) {
        int flat = tid + 512 * it;
        int r = flat >> 3, j = flat & 7;
        int gn = n0 + r;
        uint4 v = make_uint4(0, 0, 0, 0);
        if (gn < NN) v = *(const uint4*)(g_xh + (size_t)gn * 64 + j * 8);
        *(uint4*)(xs + r * PADR + j * 8) = v;
    }
    __syncthreads();

    const int m0    = wid * 16;
    const int a_row = m0 + (lane & 15);
    const int a_c8  = (lane >> 4) * 8;
    uint32_t ah[4][4];
    #pragma unroll
    for (int ks = 0; ks < 4; ks++)
        ldsm_x4(smem_u32(xs + a_row * PADR + ks * 16 + a_c8), ah[ks]);

    const int bw_r = lane & 7;
    const int bw_g = lane >> 3;
    const int g  = lane >> 2;
    const int t2 = (lane & 3) * 2;

    for (int j = 0; j < kcnt; j++) {
        const int k = kbeg + j;
        __syncthreads();
        {
            int r = tid >> 3, jc = tid & 7;
            *(uint4*)(ws + r * PADR + jc * 8) =
                *(const uint4*)(g_wt + (k << 12) + r * 64 + jc * 8);
        }
        __syncthreads();

        #pragma unroll
        for (int nt = 0; nt < 8; nt++) {
            float acc[4] = {0.f, 0.f, 0.f, 0.f};
            uint32_t bh[8];
            uint32_t row_off = (nt * 8 + bw_r) * PADR + bw_g * 8;
            ldsm_x4(smem_u32(ws + row_off), bh);
            ldsm_x4(smem_u32(ws + row_off + 32), bh + 4);
            #pragma unroll
            for (int ks = 0; ks < 4; ks++)
                mma_f16(acc, ah[ks], bh + ks * 2);
            __half2 h01 = __floats2half2_rn(acc[0], acc[1]);
            __half2 h23 = __floats2half2_rn(acc[2], acc[3]);
            *(__half2*)(xs + (m0 + g) * PADR + nt * 8 + t2)     = h01;
            *(__half2*)(xs + (m0 + g + 8) * PADR + nt * 8 + t2) = h23;
        }
        __syncthreads();
        #pragma unroll
        for (int it = 0; it < 4; it++) {
            int flat = tid + 512 * it;
            int r = flat >> 3, jc = flat & 7;
            int gn = n0 + r;
            if (gn < NN)
                *(uint4*)(g_xw + (size_t)gn * KROW + k * 64 + jc * 8) =
                    *(const uint4*)(xs + r * PADR + jc * 8);
        }
    }
}

// ---------------------------------------------------------------------------
// edge pass (launch 5): 4 edges/warp (2 per half-warp, batched loads for MLP)
// ---------------------------------------------------------------------------
__global__ __launch_bounds__(256) void edge_kernel(float* __restrict__ out) {
    const int warp   = (blockIdx.x * blockDim.x + threadIdx.x) >> 5;
    const int lane   = threadIdx.x & 31;
    const int half   = lane >> 4;
    const int sub4   = (lane & 15) * 4;
    const int nwarps = (gridDim.x * blockDim.x) >> 5;

    for (int e4 = warp * 4; e4 < EE; e4 += nwarps * 4) {
        uint4 ra = g_erec[e4 + half];
        uint4 rb = g_erec[e4 + 2 + half];

        const __half* pa = g_xw + ra.y + sub4;
        const __half* pb = g_xw + rb.y + sub4;
        unsigned ca = ra.z, cb = rb.z;

        uint2 Aa = *(const uint2*)(pa + ((ca & 255u) << 6));
        uint2 Ba = *(const uint2*)(pa + (((ca >> 8) & 255u) << 6));
        uint2 Ca = *(const uint2*)(pa + (((ca >> 16) & 255u) << 6));
        uint2 Da = *(const uint2*)(pa + ((ca >> 24) << 6));
        uint2 Ab = *(const uint2*)(pb + ((cb & 255u) << 6));
        uint2 Bb = *(const uint2*)(pb + (((cb >> 8) & 255u) << 6));
        uint2 Cb = *(const uint2*)(pb + (((cb >> 16) & 255u) << 6));
        uint2 Db = *(const uint2*)(pb + ((cb >> 24) << 6));

        {
            __half2 fh = *(const __half2*)&ra.w;
            float f0 = __low2float(fh), f1 = __high2float(fh);
            float g0 = 1.0f - f0, g1 = 1.0f - f1;
            __half2 w00 = __float2half2_rn(g0 * g1);
            __half2 w10 = __float2half2_rn(f0 * g1);
            __half2 w01 = __float2half2_rn(g0 * f1);
            __half2 w11 = __float2half2_rn(f0 * f1);
            __half2 r0 = __hmul2(w00, *(__half2*)&Aa.x);
            r0 = __hfma2(w10, *(__half2*)&Ba.x, r0);
            r0 = __hfma2(w01, *(__half2*)&Ca.x, r0);
            r0 = __hfma2(w11, *(__half2*)&Da.x, r0);
            __half2 r1 = __hmul2(w00, *(__half2*)&Aa.y);
            r1 = __hfma2(w10, *(__half2*)&Ba.y, r1);
            r1 = __hfma2(w01, *(__half2*)&Ca.y, r1);
            r1 = __hfma2(w11, *(__half2*)&Da.y, r1);
            float2 lo = __half22float2(r0);
            float2 hi = __half22float2(r1);
            float* op = out + ra.x + sub4;
            asm volatile("red.global.add.v4.f32 [%0], {%1, %2, %3, %4};"
                         :: "l"(op), "f"(lo.x), "f"(lo.y), "f"(hi.x), "f"(hi.y)
                         : "memory");
        }
        {
            __half2 fh = *(const __half2*)&rb.w;
            float f0 = __low2float(fh), f1 = __high2float(fh);
            float g0 = 1.0f - f0, g1 = 1.0f - f1;
            __half2 w00 = __float2half2_rn(g0 * g1);
            __half2 w10 = __float2half2_rn(f0 * g1);
            __half2 w01 = __float2half2_rn(g0 * f1);
            __half2 w11 = __float2half2_rn(f0 * f1);
            __half2 r0 = __hmul2(w00, *(__half2*)&Ab.x);
            r0 = __hfma2(w10, *(__half2*)&Bb.x, r0);
            r0 = __hfma2(w01, *(__half2*)&Cb.x, r0);
            r0 = __hfma2(w11, *(__half2*)&Db.x, r0);
            __half2 r1 = __hmul2(w00, *(__half2*)&Ab.y);
            r1 = __hfma2(w10, *(__half2*)&Bb.y, r1);
            r1 = __hfma2(w01, *(__half2*)&Cb.y, r1);
            r1 = __hfma2(w11, *(__half2*)&Db.y, r1);
            float2 lo = __half22float2(r0);
            float2 hi = __half22float2(r1);
            float* op = out + rb.x + sub4;
            asm volatile("red.global.add.v4.f32 [%0], {%1, %2, %3, %4};"
                         :: "l"(op), "f"(lo.x), "f"(lo.y), "f"(hi.x), "f"(hi.y)
                         : "memory");
        }
    }
}

// ---------------------------------------------------------------------------
// final (launch 6): out = out/max(deg,1) + xw[n,25,:] + bias
// ---------------------------------------------------------------------------
__global__ __launch_bounds__(256) void final_kernel(const float* __restrict__ bias,
                                                    float* __restrict__ out) {
    int i = blockIdx.x * 256 + threadIdx.x;
    if (i >= NN * 16) return;
    int n  = i >> 4;
    int c4 = (i & 15) * 4;
    float scale = 1.0f / fmaxf(g_deg[n], 1.0f);
    float4 o = *(float4*)(out + n * FOUT + c4);
    uint2 hu = *(const uint2*)(g_xw + (size_t)n * KROW + KP * 64 + c4);
    float2 rl = __half22float2(*(__half2*)&hu.x);
    float2 rh = __half22float2(*(__half2*)&hu.y);
    float4 b = *(const float4*)(bias + c4);
    o.x = o.x * scale + rl.x + b.x;
    o.y = o.y * scale + rl.y + b.y;
    o.z = o.z * scale + rh.x + b.z;
    o.w = o.w * scale + rh.y + b.w;
    *(float4*)(out + n * FOUT + c4) = o;
}

// ---------------------------------------------------------------------------
extern "C" void kernel_launch(void* const* d_in, const int* in_sizes, int n_in,
                              void* d_out, int out_size) {
    const float* x      = (const float*)d_in[0];
    const int*   ei     = (const int*)  d_in[1];
    const float* pseudo = (const float*)d_in[2];
    const float* weight = (const float*)d_in[3];
    const float* root   = (const float*)d_in[4];
    const float* bias   = (const float*)d_in[5];
    float* out = (float*)d_out;

    const int smem_bytes = (256 * PADR + 64 * PADR) * (int)sizeof(__half);
    cudaFuncSetAttribute(xw_mma, cudaFuncAttributeMaxDynamicSharedMemorySize, smem_bytes);

    fused_prep<<<(NN * 64 + 255) / 256, 256>>>(x, weight, root, ei, out);  // 0
    scan_local<<<NBLK, 1024>>>();                                          // 1
    scan_tops<<<1, 64>>>();                                                // 2
    prep_edges<<<(EE + 255) / 256, 256>>>(ei, pseudo);                     // 3

    dim3 g2((NN + 255) / 256, 6);
    xw_mma<<<g2, 512, smem_bytes>>>();                                     // 4

    edge_kernel<<<6144, 256>>>(out);                                       // 5 <- ncu

    final_kernel<<<(NN * 16 + 255) / 256, 256>>>(bias, out);               // 6
}